// round 2
// baseline (speedup 1.0000x reference)
#include <cuda_runtime.h>
#include <cuda_bf16.h>

#define Bz   16
#define Tz   512
#define Dz   384
#define Kz   3
#define ROWS (Bz*Tz)     // 8192
#define TILE 16          // rows per conv block
#define NPAIR (Dz/2)     // 192 output-channel pairs == block threads

// ---------------- scratch (device globals; no allocation allowed) ----------------
__device__ float4 g_wp1[NPAIR*Kz*(Dz/2)];  // packed w1: [pair][k][i2] = (w2p_i, w2p1_i, w2p_i1, w2p1_i1)
__device__ float4 g_wp2[NPAIR*Kz*(Dz/2)];  // packed w2
__device__ float  g_h1[ROWS*Dz];           // hidden after layer 1
__device__ float  g_h2[ROWS*Dz];           // hidden after layer 2
__device__ int    g_cum[ROWS];             // per-batch inclusive cumsum of durations

// ---------------- f32x2 helpers ----------------
__device__ __forceinline__ void ffma2(unsigned long long& d, unsigned long long a, unsigned long long b) {
    asm("fma.rn.f32x2 %0, %1, %2, %0;" : "+l"(d) : "l"(a), "l"(b));
}
__device__ __forceinline__ unsigned long long pk2(float lo, float hi) {
    unsigned long long r; asm("mov.b64 %0, {%1,%2};" : "=l"(r) : "f"(lo), "f"(hi)); return r;
}
__device__ __forceinline__ void upk2(unsigned long long v, float& lo, float& hi) {
    asm("mov.b64 {%0,%1}, %2;" : "=f"(lo), "=f"(hi) : "l"(v));
}

// ---------------- weight pack: w[O][I][K] -> wp4[pair][k][i2] ----------------
__global__ void pack_w_kernel(const float* __restrict__ w, int stage) {
    float4* wp = (stage == 0) ? g_wp1 : g_wp2;
    int idx = blockIdx.x * blockDim.x + threadIdx.x;
    const int NI2 = Dz/2;
    if (idx >= NPAIR*Kz*NI2) return;
    int i2 = idx % NI2;
    int k  = (idx / NI2) % Kz;
    int p  = idx / (NI2*Kz);
    int o0 = 2*p, i0 = 2*i2;
    // w layout: [O][I][K] -> o*Dz*Kz + i*Kz + k
    float4 v;
    v.x = w[(size_t)o0*Dz*Kz     + i0*Kz     + k];
    v.y = w[(size_t)(o0+1)*Dz*Kz + i0*Kz     + k];
    v.z = w[(size_t)o0*Dz*Kz     + (i0+1)*Kz + k];
    v.w = w[(size_t)(o0+1)*Dz*Kz + (i0+1)*Kz + k];
    wp[idx] = v;
}

// ---------------- fused conv1d(K=3,'same') + LayerNorm + ReLU, FFMA2 version ----------------
// stage 0: in = x (param), wp = g_wp1, out = g_h1
// stage 1: in = g_h1,      wp = g_wp2, out = g_h2
__global__ void __launch_bounds__(NPAIR, 3) conv_ln_relu2_kernel(
    const float* __restrict__ x_in,
    const float* __restrict__ bias,
    const float* __restrict__ gamma,
    const float* __restrict__ beta,
    int stage)
{
    extern __shared__ unsigned char smem_raw[];
    // phase 1: duplicated input patch, (TILE+2) rows x Dz float2  (55296 B)
    float4* patchw = (float4*)smem_raw;               // per row: 192 float4
    const ulonglong2* patchv = (const ulonglong2*)smem_raw;
    __shared__ float s_mean[TILE];
    __shared__ float s_rstd[TILE];

    const float*  in  = (stage == 0) ? x_in  : g_h1;
    const float4* wp  = (stage == 0) ? g_wp1 : g_wp2;
    float*        out = (stage == 0) ? g_h1  : g_h2;

    const int p = threadIdx.x;                 // channel pair (2p, 2p+1)
    const int tilesPerB = Tz / TILE;           // 32
    const int b  = blockIdx.x / tilesPerB;
    const int t0 = (blockIdx.x % tilesPerB) * TILE;
    const float* inB = in + (size_t)b * Tz * Dz;

    // load input patch duplicated: patchd[row][i] = (x, x)
    #pragma unroll
    for (int pr = 0; pr < TILE + 2; pr++) {
        int t = t0 + pr - 1;
        float2 v = make_float2(0.f, 0.f);
        if (t >= 0 && t < Tz) v = *(const float2*)(inB + (size_t)t*Dz + 2*p);
        patchw[pr*NPAIR + p] = make_float4(v.x, v.x, v.y, v.y);
    }
    __syncthreads();

    // accumulators packed over the channel pair
    unsigned long long acc[TILE];
    {
        float2 bv = *(const float2*)(bias + 2*p);
        unsigned long long b0 = pk2(bv.x, bv.y);
        #pragma unroll
        for (int r = 0; r < TILE; r++) acc[r] = b0;
    }

    // GEMM core: acc[r] += sum_k sum_i (x,x) * (w2p, w2p+1)
    const ulonglong2* wv = (const ulonglong2*)(wp + (size_t)p * Kz * (Dz/2));
    #pragma unroll
    for (int k = 0; k < Kz; k++) {
        const ulonglong2* pk = patchv + k * NPAIR;   // row r adds r*NPAIR
        #pragma unroll 2
        for (int i2 = 0; i2 < Dz/2; i2++) {
            ulonglong2 w = wv[k*(Dz/2) + i2];
            #pragma unroll
            for (int r = 0; r < TILE; r++) {
                ulonglong2 xv = pk[r*NPAIR + i2];    // smem broadcast LDS.128
                ffma2(acc[r], xv.x, w.x);
                ffma2(acc[r], xv.y, w.y);
            }
        }
    }

    // stash conv outputs in smem (reuse patch region) for LN reductions
    __syncthreads();
    float2* stash = (float2*)smem_raw;               // [TILE*NPAIR]
    #pragma unroll
    for (int r = 0; r < TILE; r++) {
        float lo, hi; upk2(acc[r], lo, hi);
        stash[r*NPAIR + p] = make_float2(lo, hi);
    }
    __syncthreads();

    // per-row mean / rstd (warp per row; 6 warps cover 16 rows)
    const int warp = p >> 5, lane = p & 31;
    for (int r = warp; r < TILE; r += 6) {
        const float* row = (const float*)(stash + r*NPAIR);  // 384 floats
        float s = 0.f, sq = 0.f;
        #pragma unroll
        for (int i = lane; i < Dz; i += 32) {
            float v = row[i];
            s += v; sq += v*v;
        }
        #pragma unroll
        for (int off = 16; off > 0; off >>= 1) {
            s  += __shfl_xor_sync(0xffffffffu, s,  off);
            sq += __shfl_xor_sync(0xffffffffu, sq, off);
        }
        if (lane == 0) {
            float m = s * (1.f/Dz);
            float var = sq * (1.f/Dz) - m*m;
            s_mean[r] = m;
            s_rstd[r] = rsqrtf(var + 1e-5f);
        }
    }
    __syncthreads();

    const float2 gg = *(const float2*)(gamma + 2*p);
    const float2 bb = *(const float2*)(beta  + 2*p);
    float* outB = out + ((size_t)b*Tz + t0) * Dz;
    #pragma unroll
    for (int r = 0; r < TILE; r++) {
        float2 cv = stash[r*NPAIR + p];
        float m = s_mean[r], rs = s_rstd[r];
        float2 o;
        o.x = fmaxf((cv.x - m) * rs * gg.x + bb.x, 0.f);
        o.y = fmaxf((cv.y - m) * rs * gg.y + bb.y, 0.f);
        *(float2*)(outB + (size_t)r*Dz + 2*p) = o;
    }
}

// ---------------- pred = h2 @ wl + bl  (warp per row) ----------------
__global__ void pred_kernel(const float* __restrict__ wl,
                            const float* __restrict__ bl,
                            float* __restrict__ pred)
{
    int row  = blockIdx.x * (blockDim.x >> 5) + (threadIdx.x >> 5);
    int lane = threadIdx.x & 31;
    if (row >= ROWS) return;
    const float* hr = g_h2 + (size_t)row * Dz;
    float s = 0.f;
    #pragma unroll
    for (int i = lane; i < Dz; i += 32) s += hr[i] * wl[i];
    #pragma unroll
    for (int off = 16; off > 0; off >>= 1) s += __shfl_xor_sync(0xffffffffu, s, off);
    if (lane == 0) pred[row] = s + bl[0];
}

// ---------------- per-batch inclusive cumsum of durations ----------------
__global__ void scan_kernel(const int* __restrict__ dur) {
    __shared__ int s[Tz];
    int b = blockIdx.x, t = threadIdx.x;
    s[t] = dur[b*Tz + t];
    __syncthreads();
    for (int off = 1; off < Tz; off <<= 1) {
        int v = (t >= off) ? s[t - off] : 0;
        __syncthreads();
        s[t] += v;
        __syncthreads();
    }
    g_cum[b*Tz + t] = s[t];
}

// ---------------- expansion: expanded[b,l,:] = x[b,j,:] with cum[j-1]<=l<cum[j] ----------------
__global__ void expand_kernel(const float* __restrict__ x,
                              float* __restrict__ out, int L)
{
    int l = blockIdx.x, b = blockIdx.y;
    const int* cb = g_cum + b*Tz;
    int total = cb[Tz - 1];
    float4* o4 = (float4*)(out + ((size_t)b*L + l) * Dz);
    int tid = threadIdx.x;                 // 96 threads, float4 each -> 384 floats
    if (l >= total) {
        o4[tid] = make_float4(0.f, 0.f, 0.f, 0.f);
        return;
    }
    int lo = 0, hi = Tz - 1;
    while (lo < hi) {                      // first j with cum[j] > l
        int mid = (lo + hi) >> 1;
        if (cb[mid] > l) hi = mid; else lo = mid + 1;
    }
    const float4* x4 = (const float4*)(x + ((size_t)b*Tz + lo) * Dz);
    o4[tid] = x4[tid];
}

// ---------------- launch ----------------
extern "C" void kernel_launch(void* const* d_in, const int* in_sizes, int n_in,
                              void* d_out, int out_size)
{
    const float* x   = (const float*)d_in[0];
    const int*   dur = (const int*)  d_in[1];
    const float* w1  = (const float*)d_in[2];
    const float* b1  = (const float*)d_in[3];
    const float* g1  = (const float*)d_in[4];
    const float* be1 = (const float*)d_in[5];
    const float* w2  = (const float*)d_in[6];
    const float* b2  = (const float*)d_in[7];
    const float* g2  = (const float*)d_in[8];
    const float* be2 = (const float*)d_in[9];
    const float* wl  = (const float*)d_in[10];
    const float* bl  = (const float*)d_in[11];
    float* out = (float*)d_out;

    // out = [expanded B*L*D | pred B*T]
    int L = (out_size - Bz*Tz) / (Bz*Dz);
    float* pred_out = out + (size_t)Bz * L * Dz;

    // opt-in >48KB dynamic smem (host-side, idempotent, not a stream op)
    const int SMEM = (TILE + 2) * Dz * (int)sizeof(float2);   // 55296
    cudaFuncSetAttribute(conv_ln_relu2_kernel,
                         cudaFuncAttributeMaxDynamicSharedMemorySize, SMEM);

    const int WN = NPAIR*Kz*(Dz/2);
    pack_w_kernel<<<(WN + 255)/256, 256>>>(w1, 0);
    pack_w_kernel<<<(WN + 255)/256, 256>>>(w2, 1);

    conv_ln_relu2_kernel<<<ROWS/TILE, NPAIR, SMEM>>>(x, b1, g1, be1, 0);
    conv_ln_relu2_kernel<<<ROWS/TILE, NPAIR, SMEM>>>(x, b2, g2, be2, 1);

    pred_kernel<<<(ROWS + 7)/8, 256>>>(wl, bl, pred_out);

    scan_kernel<<<Bz, Tz>>>(dur);
    expand_kernel<<<dim3(L, Bz), 96>>>(x, out, L);
}

// round 3
// speedup vs baseline: 3.7329x; 3.7329x over previous
#include <cuda_runtime.h>

#define Bz   16
#define Tz   512
#define Dz   384
#define Kz   3
#define ROWS (Bz*Tz)       // 8192
#define TM   64            // rows per block
#define NKS  (Kz*48)       // 144 k-steps of 8
#define NT   48            // n-tiles of 8 (384/8)
#define PSTR 388           // padded patch stride in floats (388 % 32 == 4 -> conflict-free frags)

// ---------------- scratch (device globals) ----------------
__device__ float4 g_wf1[NKS*NT*32];   // weights in mma-fragment layout (hi0,hi1,lo0,lo1)
__device__ float4 g_wf2[NKS*NT*32];
__device__ float  g_h1[ROWS*Dz];
__device__ float  g_h2[ROWS*Dz];
__device__ int    g_cum[ROWS];

__device__ __forceinline__ float tf32_trunc(float x) {
    return __uint_as_float(__float_as_uint(x) & 0xFFFFE000u);
}

__device__ __forceinline__ void mma_tf32(float* d,
    unsigned a0, unsigned a1, unsigned a2, unsigned a3,
    unsigned b0, unsigned b1)
{
    asm volatile(
        "mma.sync.aligned.m16n8k8.row.col.f32.tf32.tf32.f32 "
        "{%0,%1,%2,%3},{%4,%5,%6,%7},{%8,%9},{%0,%1,%2,%3};"
        : "+f"(d[0]), "+f"(d[1]), "+f"(d[2]), "+f"(d[3])
        : "r"(a0), "r"(a1), "r"(a2), "r"(a3), "r"(b0), "r"(b1));
}

// ---------------- weight prep: w[O][I][K] -> fragment-major hi/lo ----------------
// wf[(ks*NT + nt)*32 + lane] = (hi(b0), hi(b1), lo(b0), lo(b1))
// where for lane: tig=lane&3, gid=lane>>2; tap=ks/48, kc=ks%48;
//   b0 = W[och = nt*8+gid][ic = kc*8+tig][tap],  b1 = same with ic+4
__global__ void prep_w_kernel(const float* __restrict__ w, int stage) {
    float4* wf = stage ? g_wf2 : g_wf1;
    int idx = blockIdx.x * blockDim.x + threadIdx.x;
    if (idx >= NKS*NT*32) return;
    int lane = idx & 31;
    int nt   = (idx >> 5) % NT;
    int ks   = idx / (NT*32);
    int tig = lane & 3, gid = lane >> 2;
    int tap = ks / 48, kc = ks % 48;
    int ic0 = kc*8 + tig;
    int och = nt*8 + gid;
    float b0 = w[(size_t)och*Dz*Kz + (size_t)ic0*Kz + tap];
    float b1 = w[(size_t)och*Dz*Kz + (size_t)(ic0+4)*Kz + tap];
    float h0 = tf32_trunc(b0), h1 = tf32_trunc(b1);
    wf[idx] = make_float4(h0, h1, b0 - h0, b1 - h1);
}

// ---------------- fused conv1d(K=3) + LN + ReLU via tensor-core 3xTF32 ----------------
__global__ void __launch_bounds__(256) conv_ln_relu_mma(
    const float* __restrict__ x_in,
    const float* __restrict__ bias,
    const float* __restrict__ gamma,
    const float* __restrict__ beta,
    int stage)
{
    extern __shared__ float sm[];          // patch (TM+2)xPSTR floats; reused as C stash
    __shared__ float s_mean[TM], s_rstd[TM];

    const float*  in  = stage ? g_h1  : x_in;
    const float4* wf  = stage ? g_wf2 : g_wf1;
    float*        out = stage ? g_h2  : g_h1;

    const int tid  = threadIdx.x;
    const int warp = tid >> 5, lane = tid & 31;
    const int tig  = lane & 3, gid = lane >> 2;

    const int tilesPerB = Tz / TM;                 // 8
    const int b  = blockIdx.x / tilesPerB;
    const int t0 = (blockIdx.x % tilesPerB) * TM;
    const float* inB = in + (size_t)b * Tz * Dz;

    // ---- fill patch rows t0-1 .. t0+TM (66 rows), zero-padded at batch edges ----
    for (int i = tid; i < (TM+2)*(Dz/4); i += 256) {
        int pr = i / (Dz/4), c4 = i % (Dz/4);
        int t = t0 + pr - 1;
        float4 v = make_float4(0.f, 0.f, 0.f, 0.f);
        if (t >= 0 && t < Tz) v = *(const float4*)(inB + (size_t)t*Dz + c4*4);
        *(float4*)(sm + pr*PSTR + c4*4) = v;
    }
    __syncthreads();

    // ---- GEMM: warp covers 64 rows x 48 cols (n-tiles warp*6 .. warp*6+5) ----
    float acc[4][6][4];
    #pragma unroll
    for (int mt = 0; mt < 4; mt++)
        #pragma unroll
        for (int nl = 0; nl < 6; nl++)
            #pragma unroll
            for (int e = 0; e < 4; e++) acc[mt][nl][e] = 0.f;

    #pragma unroll 1
    for (int tap = 0; tap < Kz; tap++) {
        #pragma unroll 1
        for (int kc = 0; kc < 48; kc++) {
            const int ks = tap*48 + kc;
            const int c0 = kc*8 + tig;

            // A fragments from patch (conflict-free due to PSTR % 32 == 4)
            unsigned ahi[4][4], alo[4][4];
            #pragma unroll
            for (int mt = 0; mt < 4; mt++) {
                const float* pr = sm + (mt*16 + gid + tap) * PSTR;
                float a0 = pr[c0];
                float a1 = pr[8*PSTR + c0];
                float a2 = pr[c0 + 4];
                float a3 = pr[8*PSTR + c0 + 4];
                unsigned h0 = __float_as_uint(a0) & 0xFFFFE000u;
                unsigned h1 = __float_as_uint(a1) & 0xFFFFE000u;
                unsigned h2 = __float_as_uint(a2) & 0xFFFFE000u;
                unsigned h3 = __float_as_uint(a3) & 0xFFFFE000u;
                ahi[mt][0] = h0; alo[mt][0] = __float_as_uint(a0 - __uint_as_float(h0));
                ahi[mt][1] = h1; alo[mt][1] = __float_as_uint(a1 - __uint_as_float(h1));
                ahi[mt][2] = h2; alo[mt][2] = __float_as_uint(a2 - __uint_as_float(h2));
                ahi[mt][3] = h3; alo[mt][3] = __float_as_uint(a3 - __uint_as_float(h3));
            }

            const float4* wfk = wf + ((size_t)ks*NT + warp*6)*32 + lane;
            #pragma unroll
            for (int nl = 0; nl < 6; nl++) {
                float4 wv = wfk[nl*32];
                unsigned bh0 = __float_as_uint(wv.x), bh1 = __float_as_uint(wv.y);
                unsigned bl0 = __float_as_uint(wv.z), bl1 = __float_as_uint(wv.w);
                #pragma unroll
                for (int mt = 0; mt < 4; mt++) {
                    mma_tf32(acc[mt][nl], ahi[mt][0], ahi[mt][1], ahi[mt][2], ahi[mt][3], bh0, bh1);
                    mma_tf32(acc[mt][nl], ahi[mt][0], ahi[mt][1], ahi[mt][2], ahi[mt][3], bl0, bl1);
                    mma_tf32(acc[mt][nl], alo[mt][0], alo[mt][1], alo[mt][2], alo[mt][3], bh0, bh1);
                }
            }
        }
    }

    // ---- stash C (+bias) into smem (reuse patch region) ----
    __syncthreads();
    #pragma unroll
    for (int mt = 0; mt < 4; mt++) {
        int r0 = mt*16 + gid;
        #pragma unroll
        for (int nl = 0; nl < 6; nl++) {
            int c = warp*48 + nl*8 + tig*2;
            float bv0 = __ldg(bias + c), bv1 = __ldg(bias + c + 1);
            sm[r0*PSTR + c]       = acc[mt][nl][0] + bv0;
            sm[r0*PSTR + c + 1]   = acc[mt][nl][1] + bv1;
            sm[(r0+8)*PSTR + c]   = acc[mt][nl][2] + bv0;
            sm[(r0+8)*PSTR + c+1] = acc[mt][nl][3] + bv1;
        }
    }
    __syncthreads();

    // ---- per-row LN stats: warp w handles rows w*8 .. w*8+7 ----
    for (int r = warp*8; r < warp*8 + 8; r++) {
        const float* row = sm + r*PSTR;
        float s = 0.f, sq = 0.f;
        #pragma unroll
        for (int i = lane; i < Dz; i += 32) {
            float v = row[i];
            s += v; sq += v*v;
        }
        #pragma unroll
        for (int off = 16; off > 0; off >>= 1) {
            s  += __shfl_xor_sync(0xffffffffu, s,  off);
            sq += __shfl_xor_sync(0xffffffffu, sq, off);
        }
        if (lane == 0) {
            float m = s * (1.f/Dz);
            float var = sq * (1.f/Dz) - m*m;
            s_mean[r] = m;
            s_rstd[r] = rsqrtf(var + 1e-5f);
        }
    }
    __syncthreads();

    // ---- normalize + ReLU + store ----
    float* outB = out + ((size_t)b*Tz + t0) * Dz;
    for (int idx = tid; idx < TM*Dz; idx += 256) {
        int r = idx / Dz, c = idx - r*Dz;
        float v = sm[r*PSTR + c];
        float o = (v - s_mean[r]) * s_rstd[r] * __ldg(gamma + c) + __ldg(beta + c);
        outB[(size_t)r*Dz + c] = fmaxf(o, 0.f);
    }
}

// ---------------- pred = h2 @ wl + bl  (warp per row) ----------------
__global__ void pred_kernel(const float* __restrict__ wl,
                            const float* __restrict__ bl,
                            float* __restrict__ pred)
{
    int row  = blockIdx.x * (blockDim.x >> 5) + (threadIdx.x >> 5);
    int lane = threadIdx.x & 31;
    if (row >= ROWS) return;
    const float* hr = g_h2 + (size_t)row * Dz;
    float s = 0.f;
    #pragma unroll
    for (int i = lane; i < Dz; i += 32) s += hr[i] * wl[i];
    #pragma unroll
    for (int off = 16; off > 0; off >>= 1) s += __shfl_xor_sync(0xffffffffu, s, off);
    if (lane == 0) pred[row] = s + bl[0];
}

// ---------------- per-batch inclusive cumsum of durations ----------------
__global__ void scan_kernel(const int* __restrict__ dur) {
    __shared__ int s[Tz];
    int b = blockIdx.x, t = threadIdx.x;
    s[t] = dur[b*Tz + t];
    __syncthreads();
    for (int off = 1; off < Tz; off <<= 1) {
        int v = (t >= off) ? s[t - off] : 0;
        __syncthreads();
        s[t] += v;
        __syncthreads();
    }
    g_cum[b*Tz + t] = s[t];
}

// ---------------- expansion ----------------
__global__ void expand_kernel(const float* __restrict__ x,
                              float* __restrict__ out, int L)
{
    int l = blockIdx.x, b = blockIdx.y;
    const int* cb = g_cum + b*Tz;
    int total = cb[Tz - 1];
    float4* o4 = (float4*)(out + ((size_t)b*L + l) * Dz);
    int tid = threadIdx.x;                 // 96 threads x float4 = 384 floats
    if (l >= total) {
        o4[tid] = make_float4(0.f, 0.f, 0.f, 0.f);
        return;
    }
    int lo = 0, hi = Tz - 1;
    while (lo < hi) {
        int mid = (lo + hi) >> 1;
        if (cb[mid] > l) hi = mid; else lo = mid + 1;
    }
    const float4* x4 = (const float4*)(x + ((size_t)b*Tz + lo) * Dz);
    o4[tid] = x4[tid];
}

// ---------------- launch ----------------
extern "C" void kernel_launch(void* const* d_in, const int* in_sizes, int n_in,
                              void* d_out, int out_size)
{
    const float* x   = (const float*)d_in[0];
    const int*   dur = (const int*)  d_in[1];
    const float* w1  = (const float*)d_in[2];
    const float* b1  = (const float*)d_in[3];
    const float* g1  = (const float*)d_in[4];
    const float* be1 = (const float*)d_in[5];
    const float* w2  = (const float*)d_in[6];
    const float* b2  = (const float*)d_in[7];
    const float* g2  = (const float*)d_in[8];
    const float* be2 = (const float*)d_in[9];
    const float* wl  = (const float*)d_in[10];
    const float* bl  = (const float*)d_in[11];
    float* out = (float*)d_out;

    int L = (out_size - Bz*Tz) / (Bz*Dz);
    float* pred_out = out + (size_t)Bz * L * Dz;

    const int SMEM = (TM + 2) * PSTR * (int)sizeof(float);   // 102432 B
    cudaFuncSetAttribute(conv_ln_relu_mma,
                         cudaFuncAttributeMaxDynamicSharedMemorySize, SMEM);

    const int WN = NKS*NT*32;
    prep_w_kernel<<<(WN + 255)/256, 256>>>(w1, 0);
    prep_w_kernel<<<(WN + 255)/256, 256>>>(w2, 1);

    conv_ln_relu_mma<<<ROWS/TM, 256, SMEM>>>(x, b1, g1, be1, 0);
    conv_ln_relu_mma<<<ROWS/TM, 256, SMEM>>>(x, b2, g2, be2, 1);

    pred_kernel<<<(ROWS + 7)/8, 256>>>(wl, bl, pred_out);

    scan_kernel<<<Bz, Tz>>>(dur);
    expand_kernel<<<dim3(L, Bz), 96>>>(x, out, L);
}